// round 7
// baseline (speedup 1.0000x reference)
#include <cuda_runtime.h>

// ---------------- problem constants ----------------
#define IN_DIM 256
#define KTOT   33152          // FEAT = 259 chunks of 128
#define NTOT   8192
#define BATCH  8
#define S_DIM  32
#define OUT_F  64

// ---------------- gemm tiling ----------------
#define CHUNK   128
#define NCHUNK  (KTOT / CHUNK)           // 259
#define KTILE   512                      // feats tile = 4 chunks
#define NTILE   ((KTOT + KTILE - 1) / KTILE)  // 65 (last tile = 3 chunks)
#define STAGES  4
#define TCOLS   7                        // columns per warp
#define WARPS   4                        // 128 threads
#define COLS_PER_BLOCK (WARPS * TCOLS)   // 28
#define GEMM_BLOCKS 296                  // 148 SMs x 2 — uniform
#define W_STAGE_FLOATS (COLS_PER_BLOCK * CHUNK)            // 3584
#define SMEM_FLOATS (STAGES * W_STAGE_FLOATS + 2 * BATCH * KTILE) // 22528
#define SMEM_BYTES  (SMEM_FLOATS * 4)    // 90112

__device__ float g_feats[BATCH * KTOT];
__device__ float g_head [BATCH * NTOT];

using u64 = unsigned long long;
union F4U { float4 f4; u64 u[2]; float f[4]; };
union F2U { u64 u; float f[2]; };

__device__ __forceinline__ u64 ffma2(u64 a, u64 b, u64 c) {
    u64 d;
    asm("fma.rn.f32x2 %0, %1, %2, %3;" : "=l"(d) : "l"(a), "l"(b), "l"(c));
    return d;
}
__device__ __forceinline__ void cpa16(float* dst, const float* src) {
    unsigned s = (unsigned)__cvta_generic_to_shared(dst);
    asm volatile("cp.async.cg.shared.global [%0], [%1], 16;" :: "r"(s), "l"(src) : "memory");
}
__device__ __forceinline__ void cpa_commit() {
    asm volatile("cp.async.commit_group;" ::: "memory");
}
__device__ __forceinline__ void cpa_wait3() {
    asm volatile("cp.async.wait_group 3;" ::: "memory");
}

// ---------------------------------------------------------------
// Kernel 1: build features
// ---------------------------------------------------------------
__global__ void feat_kernel(const float* __restrict__ x) {
    const int i = blockIdx.x, b = blockIdx.y, j = threadIdx.x;
    __shared__ float sx[IN_DIM];
    sx[j] = x[b * IN_DIM + j];
    __syncthreads();
    float* gb = g_feats + (size_t)b * KTOT;
    if (i == 0) gb[j] = sx[j];
    if (j >= i) {
        int off = 256 * i - (i * (i - 1)) / 2;
        gb[IN_DIM + off + (j - i)] = sx[i] * sx[j];
    }
}

// ---------------------------------------------------------------
// Kernel 2: head GEMM — cp.async 4-stage W ring.
//   128 threads (4 warps x 7 cols), grid 296 uniform, occ 2 ->
//   255-reg budget, 56 u64 accumulators, no spills.
//   Warp w loads AND consumes cols 7w..7w+6 (warp-local visibility:
//   per-thread wait_group 3 + __syncwarp).
// ---------------------------------------------------------------
__global__ void __launch_bounds__(WARPS * 32, 2)
gemm_kernel(const float* __restrict__ W, const float* __restrict__ bh) {
    extern __shared__ __align__(16) float smem[];
    float* sw = smem;                               // [STAGES][28][128]
    float* sf = smem + STAGES * W_STAGE_FLOATS;     // [2][8][512]

    const int tid  = threadIdx.x;
    const int warp = tid >> 5;
    const int lane = tid & 31;
    const int n0   = blockIdx.x * COLS_PER_BLOCK + warp * TCOLS;

    // W source rows for this warp's 7 cols (clamped for tail blocks)
    const float* wsrc[TCOLS];
#pragma unroll
    for (int t = 0; t < TCOLS; t++) {
        int r = n0 + t;
        if (r > NTOT - 1) r = NTOT - 1;
        wsrc[t] = W + (size_t)r * KTOT + lane * 4;
    }
    // smem W base for this warp (per stage add stage*W_STAGE_FLOATS)
    float* swm = sw + warp * TCOLS * CHUNK + lane * 4;

    u64 acc[TCOLS][BATCH];
#pragma unroll
    for (int t = 0; t < TCOLS; t++)
#pragma unroll
        for (int b = 0; b < BATCH; b++) acc[t][b] = 0ull;

    // ---- prologue: groups 0..2 = W chunks 0..2 (+ feats tile 0 in G0)
#pragma unroll
    for (int c = 0; c < STAGES - 1; c++) {
#pragma unroll
        for (int t = 0; t < TCOLS; t++)
            cpa16(swm + c * W_STAGE_FLOATS + t * CHUNK, wsrc[t] + c * CHUNK);
        if (c == 0) {   // feats tile 0 -> buffer 0
            for (int idx = tid; idx < BATCH * (KTILE / 4); idx += WARPS * 32) {
                int b = idx >> 7, r = idx & 127;   // KTILE/4 = 128
                cpa16(sf + b * KTILE + r * 4, g_feats + (size_t)b * KTOT + r * 4);
            }
        }
        cpa_commit();
    }
    asm volatile("cp.async.wait_group 2;" ::: "memory");  // G0 (feats t0) done
    __syncthreads();

    // ---- main loop over 259 chunks
    for (int kk = 0; kk < NCHUNK; kk++) {
        if ((kk & 3) == 0 && kk != 0)
            __syncthreads();   // tile swap: all warps done with old feats buf

        // issue W chunk kk+3
        const int p = kk + STAGES - 1;
        if (p < NCHUNK) {
#pragma unroll
            for (int t = 0; t < TCOLS; t++)
                cpa16(swm + (p & 3) * W_STAGE_FLOATS + t * CHUNK,
                      wsrc[t] + (size_t)p * CHUNK);
        }
        // issue feats tile (kk/4)+1 at tile starts
        if ((kk & 3) == 0) {
            const int Tn = (kk >> 2) + 1;
            if (Tn < NTILE) {
                const int k0 = Tn * KTILE;
                const int nv = (KTOT - k0 < KTILE ? KTOT - k0 : KTILE) >> 2; // 128 or 96
                float* fdst = sf + (Tn & 1) * BATCH * KTILE;
                for (int idx = tid; idx < BATCH * nv; idx += WARPS * 32) {
                    int b = idx / nv, r = idx - b * nv;
                    cpa16(fdst + b * KTILE + r * 4,
                          g_feats + (size_t)b * KTOT + k0 + r * 4);
                }
            }
        }
        cpa_commit();
        cpa_wait3();           // chunk kk resident (this thread's copies)
        __syncwarp();          // my warp's 7 cols fully visible

        // ---- compute chunk kk
        const float* wp = swm + (kk & 3) * W_STAGE_FLOATS;
        F4U w[TCOLS];
#pragma unroll
        for (int t = 0; t < TCOLS; t++)
            w[t].f4 = *(const float4*)(wp + t * CHUNK);

        const float* fp = sf + ((kk >> 2) & 1) * BATCH * KTILE + (kk & 3) * CHUNK + lane * 4;
#pragma unroll
        for (int b = 0; b < BATCH; b++) {
            F4U fe; fe.f4 = *(const float4*)(fp + b * KTILE);
#pragma unroll
            for (int t = 0; t < TCOLS; t++) {
                acc[t][b] = ffma2(fe.u[0], w[t].u[0], acc[t][b]);
                acc[t][b] = ffma2(fe.u[1], w[t].u[1], acc[t][b]);
            }
        }
    }

    // ---- lane reduction + bias + store (guard tail cols)
#pragma unroll
    for (int t = 0; t < TCOLS; t++) {
        const int n = n0 + t;
        if (n < NTOT) {
            const float bias = bh[n];
#pragma unroll
            for (int b = 0; b < BATCH; b++) {
                F2U a; a.u = acc[t][b];
                float s = a.f[0] + a.f[1];
#pragma unroll
                for (int off = 16; off; off >>= 1)
                    s += __shfl_xor_sync(0xffffffffu, s, off);
                if (lane == 0)
                    g_head[b * NTOT + n] = s + bias;
            }
        }
    }
}

// ---------------------------------------------------------------
// Kernel 3: output projection
// ---------------------------------------------------------------
__global__ void out_kernel(const float* __restrict__ Wout,
                           const float* __restrict__ bout,
                           float* __restrict__ out) {
    const int bs = blockIdx.x;
    const int b = bs >> 5, s = bs & 31;
    __shared__ __align__(16) float row[256];
    const int tid = threadIdx.x;

    for (int c = tid; c < 256; c += 64) {
        int h = c >> 6, d = c & 63;
        row[c] = g_head[b * NTOT + h * (S_DIM * 64) + s * 64 + d];
    }
    __syncthreads();

    float acc = bout[tid];
    const float4* wr = (const float4*)(Wout + tid * 256);
    const float4* rr = (const float4*)row;
#pragma unroll
    for (int q = 0; q < 64; q++) {
        float4 w = wr[q];
        float4 r = rr[q];
        acc += w.x * r.x + w.y * r.y + w.z * r.z + w.w * r.w;
    }
    out[bs * 64 + tid] = acc;
}

// ---------------------------------------------------------------
extern "C" void kernel_launch(void* const* d_in, const int* in_sizes, int n_in,
                              void* d_out, int out_size) {
    const float* input   = (const float*)d_in[0];
    const float* W_heads = (const float*)d_in[1];
    const float* b_heads = (const float*)d_in[2];
    const float* W_out   = (const float*)d_in[3];
    const float* b_out   = (const float*)d_in[4];
    float* out = (float*)d_out;

    cudaFuncSetAttribute(gemm_kernel,
                         cudaFuncAttributeMaxDynamicSharedMemorySize, SMEM_BYTES);

    dim3 g1(IN_DIM, BATCH);
    feat_kernel<<<g1, IN_DIM>>>(input);
    gemm_kernel<<<GEMM_BLOCKS, WARPS * 32, SMEM_BYTES>>>(W_heads, b_heads);
    out_kernel<<<BATCH * S_DIM, OUT_F>>>(W_out, b_out, out);
}